// round 3
// baseline (speedup 1.0000x reference)
#include <cuda_runtime.h>
#include <cuda_bf16.h>
#include <math.h>

#define DDIM 512
#define PCNT 64
#define NTHREADS 256

__global__ __launch_bounds__(NTHREADS) void proto_match_kernel(
    const float* __restrict__ feats,     // [N, D]
    const float* __restrict__ protos,    // [C, P, D]
    const int*   __restrict__ cls_ids,   // [N]
    const int*   __restrict__ plabels,   // [C, P]
    float* __restrict__ out,             // [N + N*P]: labels then probs
    int N)
{
    const int n    = blockIdx.x;
    const int tid  = threadIdx.x;
    const int lane = tid & 31;
    const int wid  = tid >> 5;

    __shared__ float f[DDIM];
    __shared__ float dd[3][PCNT];    // d_cos, d_l1, d_l2
    __shared__ float pm[3][PCNT];    // per-metric softmax probs
    __shared__ float red[8];
    __shared__ float fnorm_sh;
    __shared__ float avg[PCNT];

    // ---- load feature vector into smem, compute ||f|| ----
    const float* fptr = feats + (size_t)n * DDIM;
    float sq = 0.f;
    for (int i = tid; i < DDIM; i += NTHREADS) {
        float v = fptr[i];
        f[i] = v;
        sq += v * v;
    }
    #pragma unroll
    for (int o = 16; o > 0; o >>= 1) sq += __shfl_down_sync(0xffffffffu, sq, o);
    if (lane == 0) red[wid] = sq;
    __syncthreads();
    if (tid == 0) {
        float s = 0.f;
        #pragma unroll
        for (int i = 0; i < 8; i++) s += red[i];
        fnorm_sh = fmaxf(sqrtf(s), 1e-8f);
    }
    __syncthreads();
    const float fnorm = fnorm_sh;

    const int c = cls_ids[n];
    const float* pbase = protos + ((size_t)c * PCNT) * DDIM;
    const float4* fv = reinterpret_cast<const float4*>(f);

    // ---- each warp: 8 prototypes ----
    for (int p = wid; p < PCNT; p += 8) {
        const float4* pv = reinterpret_cast<const float4*>(pbase + (size_t)p * DDIM);
        float dot = 0.f, pn = 0.f, l1 = 0.f, l2 = 0.f;
        #pragma unroll
        for (int j = 0; j < 4; j++) {
            int idx = lane + 32 * j;        // 128 float4 per row
            float4 a = __ldg(&pv[idx]);
            float4 b = fv[idx];
            dot += a.x*b.x + a.y*b.y + a.z*b.z + a.w*b.w;
            pn  += a.x*a.x + a.y*a.y + a.z*a.z + a.w*a.w;
            float dx = b.x - a.x, dy = b.y - a.y, dz = b.z - a.z, dw = b.w - a.w;
            l1 += fabsf(dx) + fabsf(dy) + fabsf(dz) + fabsf(dw);
            l2 += dx*dx + dy*dy + dz*dz + dw*dw;
        }
        #pragma unroll
        for (int o = 16; o > 0; o >>= 1) {
            dot += __shfl_down_sync(0xffffffffu, dot, o);
            pn  += __shfl_down_sync(0xffffffffu, pn,  o);
            l1  += __shfl_down_sync(0xffffffffu, l1,  o);
            l2  += __shfl_down_sync(0xffffffffu, l2,  o);
        }
        if (lane == 0) {
            float pnorm = fmaxf(sqrtf(pn), 1e-8f);
            dd[0][p] = 1.f - dot / (fnorm * pnorm);
            dd[1][p] = l1 * (1.f / DDIM);
            dd[2][p] = l2 * (1.f / DDIM);
        }
    }
    __syncthreads();

    // ---- softmax of 1/(d+1e-5) over P, one warp per metric ----
    if (wid < 3) {
        float s0 = 1.f / (dd[wid][lane]      + 1e-5f);
        float s1 = 1.f / (dd[wid][lane + 32] + 1e-5f);
        float m = fmaxf(s0, s1);
        #pragma unroll
        for (int o = 16; o > 0; o >>= 1) m = fmaxf(m, __shfl_xor_sync(0xffffffffu, m, o));
        float e0 = expf(s0 - m), e1 = expf(s1 - m);
        float sum = e0 + e1;
        #pragma unroll
        for (int o = 16; o > 0; o >>= 1) sum += __shfl_xor_sync(0xffffffffu, sum, o);
        float inv = 1.f / sum;
        pm[wid][lane]      = e0 * inv;
        pm[wid][lane + 32] = e1 * inv;
    }
    __syncthreads();

    // ---- average over 3 metrics, write probs ----
    if (tid < PCNT) {
        float a = (pm[0][tid] + pm[1][tid] + pm[2][tid]) * (1.f / 3.f);
        avg[tid] = a;
        out[(size_t)N + (size_t)n * PCNT + tid] = a;
    }
    __syncthreads();

    // ---- argmax (first occurrence on ties) + label ----
    if (wid == 0) {
        float a0 = avg[lane];
        float a1 = avg[lane + 32];
        int   i0 = lane;
        if (a1 > a0) { a0 = a1; i0 = lane + 32; }
        #pragma unroll
        for (int o = 16; o > 0; o >>= 1) {
            float ao = __shfl_xor_sync(0xffffffffu, a0, o);
            int   io = __shfl_xor_sync(0xffffffffu, i0, o);
            if (ao > a0 || (ao == a0 && io < i0)) { a0 = ao; i0 = io; }
        }
        if (lane == 0) {
            out[n] = (float)plabels[c * PCNT + i0];
        }
    }
}

extern "C" void kernel_launch(void* const* d_in, const int* in_sizes, int n_in,
                              void* d_out, int out_size) {
    const float* feats   = (const float*)d_in[0];   // [N, 512]
    const float* protos  = (const float*)d_in[1];   // [100, 64, 512]
    const int*   cls_ids = (const int*)d_in[2];     // [N]
    const int*   plabels = (const int*)d_in[3];     // [100, 64]
    float* out = (float*)d_out;

    int N = in_sizes[0] / DDIM;   // 4096

    proto_match_kernel<<<N, NTHREADS>>>(feats, protos, cls_ids, plabels, out, N);
}

// round 6
// speedup vs baseline: 1.2617x; 1.2617x over previous
#include <cuda_runtime.h>
#include <cuda_bf16.h>
#include <math.h>

#define DDIM 512
#define PCNT 64
#define NTHREADS 256
#define CCNT 100

__device__ float g_psq[CCNT * PCNT];   // precomputed ||p||^2 per prototype

// ---- prologue: ||p||^2 for every prototype row (one warp per row) ----
__global__ __launch_bounds__(NTHREADS) void psq_kernel(
    const float* __restrict__ protos)
{
    const int row  = blockIdx.x * 8 + (threadIdx.x >> 5);   // C*P = 6400 rows
    const int lane = threadIdx.x & 31;
    if (row >= CCNT * PCNT) return;
    const float4* pv = reinterpret_cast<const float4*>(protos + (size_t)row * DDIM);
    float s = 0.f;
    #pragma unroll
    for (int j = 0; j < 4; j++) {
        float4 a = __ldg(&pv[lane + 32 * j]);
        s += a.x*a.x + a.y*a.y + a.z*a.z + a.w*a.w;
    }
    #pragma unroll
    for (int o = 16; o > 0; o >>= 1) s += __shfl_down_sync(0xffffffffu, s, o);
    if (lane == 0) g_psq[row] = s;
}

__global__ __launch_bounds__(NTHREADS) void proto_match_kernel(
    const float* __restrict__ feats,     // [N, D]
    const float* __restrict__ protos,    // [C, P, D]
    const int*   __restrict__ cls_ids,   // [N]
    const int*   __restrict__ plabels,   // [C, P]
    float* __restrict__ out,             // [N + N*P]: labels then probs
    int N)
{
    const int n    = blockIdx.x;
    const int tid  = threadIdx.x;
    const int lane = tid & 31;
    const int wid  = tid >> 5;

    __shared__ float f[DDIM];
    __shared__ float dot_sh[PCNT];
    __shared__ float l1_sh[PCNT];
    __shared__ float dd[3][PCNT];
    __shared__ float pm[3][PCNT];
    __shared__ float red[8];
    __shared__ float fnorm_sh, fsq_sh;
    __shared__ float avg[PCNT];

    // ---- stage feature vector, compute ||f||^2 ----
    const float* fptr = feats + (size_t)n * DDIM;
    float sq = 0.f;
    for (int i = tid; i < DDIM; i += NTHREADS) {
        float v = fptr[i];
        f[i] = v;
        sq += v * v;
    }
    #pragma unroll
    for (int o = 16; o > 0; o >>= 1) sq += __shfl_down_sync(0xffffffffu, sq, o);
    if (lane == 0) red[wid] = sq;
    __syncthreads();
    if (tid == 0) {
        float s = 0.f;
        #pragma unroll
        for (int i = 0; i < 8; i++) s += red[i];
        fsq_sh   = s;
        fnorm_sh = fmaxf(sqrtf(s), 1e-8f);
    }
    __syncthreads();

    // feature chunk lives in registers: 4 x float4 per lane, strided layout
    const float4* fv = reinterpret_cast<const float4*>(f);
    float4 b0 = fv[lane +  0];
    float4 b1 = fv[lane + 32];
    float4 b2 = fv[lane + 64];
    float4 b3 = fv[lane + 96];

    const int c = cls_ids[n];
    const float* pbase = protos + ((size_t)c * PCNT) * DDIM;

    // ---- each warp: 8 prototypes; inner = dot + l1 only ----
    #pragma unroll
    for (int it = 0; it < 8; it++) {
        const int p = wid + 8 * it;
        const float4* pv = reinterpret_cast<const float4*>(pbase + (size_t)p * DDIM);
        float4 a0 = __ldg(&pv[lane +  0]);
        float4 a1 = __ldg(&pv[lane + 32]);
        float4 a2 = __ldg(&pv[lane + 64]);
        float4 a3 = __ldg(&pv[lane + 96]);

        float dot = 0.f, l1 = 0.f;
        {
            dot += a0.x*b0.x + a0.y*b0.y + a0.z*b0.z + a0.w*b0.w;
            l1  += fabsf(b0.x-a0.x) + fabsf(b0.y-a0.y) + fabsf(b0.z-a0.z) + fabsf(b0.w-a0.w);
            dot += a1.x*b1.x + a1.y*b1.y + a1.z*b1.z + a1.w*b1.w;
            l1  += fabsf(b1.x-a1.x) + fabsf(b1.y-a1.y) + fabsf(b1.z-a1.z) + fabsf(b1.w-a1.w);
            dot += a2.x*b2.x + a2.y*b2.y + a2.z*b2.z + a2.w*b2.w;
            l1  += fabsf(b2.x-a2.x) + fabsf(b2.y-a2.y) + fabsf(b2.z-a2.z) + fabsf(b2.w-a2.w);
            dot += a3.x*b3.x + a3.y*b3.y + a3.z*b3.z + a3.w*b3.w;
            l1  += fabsf(b3.x-a3.x) + fabsf(b3.y-a3.y) + fabsf(b3.z-a3.z) + fabsf(b3.w-a3.w);
        }
        #pragma unroll
        for (int o = 16; o > 0; o >>= 1) {
            dot += __shfl_down_sync(0xffffffffu, dot, o);
            l1  += __shfl_down_sync(0xffffffffu, l1,  o);
        }
        if (lane == 0) { dot_sh[p] = dot; l1_sh[p] = l1; }
    }
    __syncthreads();

    // ---- distances from reductions + precomputed psq ----
    if (tid < PCNT) {
        const float fsq   = fsq_sh;
        const float fnorm = fnorm_sh;
        float dot = dot_sh[tid];
        float psq = g_psq[c * PCNT + tid];
        float pnorm = fmaxf(sqrtf(psq), 1e-8f);
        dd[0][tid] = 1.f - dot / (fnorm * pnorm);
        dd[1][tid] = l1_sh[tid] * (1.f / DDIM);
        dd[2][tid] = (fsq - 2.f * dot + psq) * (1.f / DDIM);
    }
    __syncthreads();

    // ---- softmax of 1/(d+1e-5) over P, one warp per metric ----
    if (wid < 3) {
        float s0 = 1.f / (dd[wid][lane]      + 1e-5f);
        float s1 = 1.f / (dd[wid][lane + 32] + 1e-5f);
        float m = fmaxf(s0, s1);
        #pragma unroll
        for (int o = 16; o > 0; o >>= 1) m = fmaxf(m, __shfl_xor_sync(0xffffffffu, m, o));
        float e0 = expf(s0 - m), e1 = expf(s1 - m);
        float sum = e0 + e1;
        #pragma unroll
        for (int o = 16; o > 0; o >>= 1) sum += __shfl_xor_sync(0xffffffffu, sum, o);
        float inv = 1.f / sum;
        pm[wid][lane]      = e0 * inv;
        pm[wid][lane + 32] = e1 * inv;
    }
    __syncthreads();

    // ---- average over metrics, write probs ----
    if (tid < PCNT) {
        float a = (pm[0][tid] + pm[1][tid] + pm[2][tid]) * (1.f / 3.f);
        avg[tid] = a;
        out[(size_t)N + (size_t)n * PCNT + tid] = a;
    }
    __syncthreads();

    // ---- argmax (first occurrence on ties) + label ----
    if (wid == 0) {
        float a0 = avg[lane];
        float a1 = avg[lane + 32];
        int   i0 = lane;
        if (a1 > a0) { a0 = a1; i0 = lane + 32; }
        #pragma unroll
        for (int o = 16; o > 0; o >>= 1) {
            float ao = __shfl_xor_sync(0xffffffffu, a0, o);
            int   io = __shfl_xor_sync(0xffffffffu, i0, o);
            if (ao > a0 || (ao == a0 && io < i0)) { a0 = ao; i0 = io; }
        }
        if (lane == 0) {
            out[n] = (float)plabels[c * PCNT + i0];
        }
    }
}

extern "C" void kernel_launch(void* const* d_in, const int* in_sizes, int n_in,
                              void* d_out, int out_size) {
    const float* feats   = (const float*)d_in[0];   // [N, 512]
    const float* protos  = (const float*)d_in[1];   // [100, 64, 512]
    const int*   cls_ids = (const int*)d_in[2];     // [N]
    const int*   plabels = (const int*)d_in[3];     // [100, 64]
    float* out = (float*)d_out;

    int N = in_sizes[0] / DDIM;   // 4096

    psq_kernel<<<(CCNT * PCNT + 7) / 8, NTHREADS>>>(protos);
    proto_match_kernel<<<N, NTHREADS>>>(feats, protos, cls_ids, plabels, out, N);
}